// round 11
// baseline (speedup 1.0000x reference)
#include <cuda_runtime.h>
#include <cuda_bf16.h>
#include <cstdint>
#include <math.h>

#define N_ROWS 32768
#define DIM    64
#define NEMB   8192

// ---- output layout (concatenated reference tuple, all float32) ----
#define OFF_Q    0
#define OFF_LOSS 2097152
#define OFF_IDX  2097153
#define OFF_PERP 2129921
#define OFF_W    2129922
#define OFF_CC   2654210
#define OFF_WS   2662402

// ---- argmin tiling ----
#define RPB   128            // rows per block (M)
#define CPC   128            // codes per chunk (N)
#define NCH   (NEMB/CPC)     // 64 chunks
#define NTHR  512            // 16 warps: 4(M) x 4(N)

// SMEM layout (bytes). Tiles: 128 rows x 128B (64 bf16), XOR-swizzled.
#define A_OFF      0                      // 3 x 16KB (h,m,l splits of x rows)
#define B_OFF      49152                  // 2 bufs x 3 x 16KB
#define SEN_OFF    147456                 // 2 x 512B (0.5*||e||^2 per chunk)
#define RED_OFF    148480                 // 128 rows x 4 warpcols x 8B
#define SMEM_BYTES 152576

// ---- device scratch ----
__device__ int   g_idx[N_ROWS];
__device__ float g_counts[NEMB];
__device__ float g_embsum[NEMB * DIM];
__device__ float g_enormh[NEMB];
__device__ float g_nsum;
__device__ float g_loss;
__device__ float g_plogp;
// pre-split codebook (3-term bf16 decomposition of w)
__device__ __nv_bfloat16 g_wh[NEMB * DIM];
__device__ __nv_bfloat16 g_wm[NEMB * DIM];
__device__ __nv_bfloat16 g_wl[NEMB * DIM];

// ================= helpers =================
__device__ __forceinline__ uint32_t smem_u32_of(const void* p) {
    uint32_t a;
    asm("{ .reg .u64 t; cvta.to.shared.u64 t, %1; cvt.u32.u64 %0, t; }"
        : "=r"(a) : "l"(p));
    return a;
}
__device__ __forceinline__ void ldmx4(uint32_t& r0, uint32_t& r1, uint32_t& r2,
                                      uint32_t& r3, uint32_t a) {
    asm volatile("ldmatrix.sync.aligned.m8n8.x4.shared.b16 {%0,%1,%2,%3}, [%4];"
                 : "=r"(r0), "=r"(r1), "=r"(r2), "=r"(r3) : "r"(a));
}
__device__ __forceinline__ void mma16816(float& c0, float& c1, float& c2, float& c3,
                                         uint32_t a0, uint32_t a1, uint32_t a2, uint32_t a3,
                                         uint32_t b0, uint32_t b1) {
    asm volatile("mma.sync.aligned.m16n8k16.row.col.f32.bf16.bf16.f32 "
                 "{%0,%1,%2,%3}, {%4,%5,%6,%7}, {%8,%9}, {%0,%1,%2,%3};"
                 : "+f"(c0), "+f"(c1), "+f"(c2), "+f"(c3)
                 : "r"(a0), "r"(a1), "r"(a2), "r"(a3), "r"(b0), "r"(b1));
}
__device__ __forceinline__ void cp16(uint32_t dst, const void* src) {
    asm volatile("cp.async.cg.shared.global [%0], [%1], 16;" :: "r"(dst), "l"(src));
}
#define CP_COMMIT() asm volatile("cp.async.commit_group;" ::: "memory")
#define CP_WAIT0()  asm volatile("cp.async.wait_group 0;" ::: "memory")

__device__ __forceinline__ uint32_t pack_bf2(__nv_bfloat16 a, __nv_bfloat16 b) {
    unsigned short ua = *(unsigned short*)&a, ub = *(unsigned short*)&b;
    return (uint32_t)ua | ((uint32_t)ub << 16);
}
__device__ __forceinline__ unsigned long long pack_key(float s, int j) {
    uint32_t u = __float_as_uint(s);
    u = (u & 0x80000000u) ? ~u : (u | 0x80000000u);   // order-preserving
    return ((unsigned long long)u << 32) | (uint32_t)(~j);  // bigger = better; ties -> smaller j
}

// ============================================================
__global__ void k_init() {
    int t = blockIdx.x * 256 + threadIdx.x;
    if (t < NEMB * DIM) g_embsum[t] = 0.f;
    if (t < NEMB)       g_counts[t] = 0.f;
    if (t == 0) { g_nsum = 0.f; g_loss = 0.f; g_plogp = 0.f; }
}

// 3-way bf16 split of the codebook
__global__ void k_prep(const float* __restrict__ w) {
    int t = blockIdx.x * 256 + threadIdx.x;
    float v = w[t];
    __nv_bfloat16 h = __float2bfloat16_rn(v);
    float r1 = v - __bfloat162float(h);
    __nv_bfloat16 m = __float2bfloat16_rn(r1);
    float r2 = r1 - __bfloat162float(m);
    __nv_bfloat16 l = __float2bfloat16_rn(r2);
    g_wh[t] = h; g_wm[t] = m; g_wl[t] = l;
}

__global__ void k_enorm(const float* __restrict__ w) {
    int code = blockIdx.x * 8 + (threadIdx.x >> 5);
    int lane = threadIdx.x & 31;
    float a = w[code * DIM + lane];
    float b = w[code * DIM + 32 + lane];
    float s = a * a + b * b;
#pragma unroll
    for (int m = 16; m >= 1; m >>= 1) s += __shfl_xor_sync(0xffffffffu, s, m);
    if (lane == 0) g_enormh[code] = 0.5f * s;
}

// ============================================================
// tensor-core argmin via mma.sync. 512 threads: warp grid 4Mx4N,
// warp tile 32x32 (acc[2][4][4] = 32 regs) -> 16 warps/SM for
// latency hiding (R9 bottleneck: occ 12.5%, tensor pipe 49%).
// ============================================================
__device__ __forceinline__ void prefetch_chunk(uint32_t sb, int buf, int cbase, int tid) {
    const __nv_bfloat16* wsp0 = g_wh;
    const __nv_bfloat16* wsp1 = g_wm;
    const __nv_bfloat16* wsp2 = g_wl;
#pragma unroll
    for (int i = 0; i < 6; i++) {
        int u = tid + i * NTHR;               // 3 splits * 128 rows * 8 col16 = 3072
        int s = u >> 10;
        int rem = u & 1023;
        int row = rem >> 3, c16 = rem & 7;
        uint32_t dst = sb + B_OFF + buf * 49152 + s * 16384 +
                       row * 128 + (((uint32_t)(c16 ^ (row & 7))) << 4);
        const __nv_bfloat16* wsp = (s == 0) ? wsp0 : (s == 1) ? wsp1 : wsp2;
        cp16(dst, wsp + (size_t)(cbase + row) * 64 + c16 * 8);
    }
    if (tid >= NTHR - 32) {                   // sen: 128 floats = 32 x 16B
        int u = tid - (NTHR - 32);
        cp16(sb + SEN_OFF + buf * 512 + u * 16, g_enormh + cbase + u * 4);
    }
    CP_COMMIT();
}

__global__ void __launch_bounds__(NTHR, 1) k_argmin_mma(const float* __restrict__ x,
                                                        float* __restrict__ out_idxf) {
    extern __shared__ __align__(16) char smem[];
    uint32_t sb = smem_u32_of(smem);
    int tid = threadIdx.x;
    int wid = tid >> 5;
    int lid = tid & 31;
    int rowBase = blockIdx.x * RPB;

    int wr = wid & 3;          // M slab (32 rows)
    int wc = wid >> 2;         // N slab (32 codes)
    int Mbase = wr * 32;
    int Nbase = wc * 32;

    // ldmatrix lane geometry (same for A and B)
    int ri    = lid & 7;
    int mi    = lid >> 3;
    int rowIn = (mi & 1) * 8 + ri;   // row within 16-row tile
    int half  = mi >> 1;             // col16 half within tile
    uint32_t colk[4];
#pragma unroll
    for (int kt = 0; kt < 4; kt++) colk[kt] = (uint32_t)((kt * 2 + half) ^ ri) << 4;
    uint32_t aLane = sb + A_OFF + (uint32_t)(Mbase + rowIn) * 128;
    uint32_t bLane = sb + B_OFF + (uint32_t)(Nbase + rowIn) * 128;

    // kick off B prefetch for chunk 0
    prefetch_chunk(sb, 0, 0, tid);

    // ---- A fill: split 128x64 f32 rows into 3 swizzled bf16 tiles ----
#pragma unroll
    for (int i = 0; i < 2; i++) {
        int u = tid + i * NTHR;              // 128 rows * 8 col16 = 1024
        int row = u >> 3, c16 = u & 7;
        const float* src = x + (size_t)(rowBase + row) * 64 + c16 * 8;
        float4 f0 = *(const float4*)src;
        float4 f1 = *(const float4*)(src + 4);
        float v[8] = {f0.x, f0.y, f0.z, f0.w, f1.x, f1.y, f1.z, f1.w};
        __nv_bfloat16 hb[8], mb[8], lb[8];
#pragma unroll
        for (int j = 0; j < 8; j++) {
            __nv_bfloat16 h = __float2bfloat16_rn(v[j]);
            float r1 = v[j] - __bfloat162float(h);
            __nv_bfloat16 m = __float2bfloat16_rn(r1);
            float r2 = r1 - __bfloat162float(m);
            hb[j] = h; mb[j] = m; lb[j] = __float2bfloat16_rn(r2);
        }
        uint32_t off = (uint32_t)row * 128 + (((uint32_t)(c16 ^ (row & 7))) << 4);
        uint4 ph = make_uint4(pack_bf2(hb[0], hb[1]), pack_bf2(hb[2], hb[3]),
                              pack_bf2(hb[4], hb[5]), pack_bf2(hb[6], hb[7]));
        uint4 pm = make_uint4(pack_bf2(mb[0], mb[1]), pack_bf2(mb[2], mb[3]),
                              pack_bf2(mb[4], mb[5]), pack_bf2(mb[6], mb[7]));
        uint4 pl = make_uint4(pack_bf2(lb[0], lb[1]), pack_bf2(lb[2], lb[3]),
                              pack_bf2(lb[4], lb[5]), pack_bf2(lb[6], lb[7]));
        *(uint4*)(smem + A_OFF + off)           = ph;
        *(uint4*)(smem + A_OFF + 16384 + off)   = pm;
        *(uint4*)(smem + A_OFF + 32768 + off)   = pl;
    }

    CP_WAIT0();
    __syncthreads();

    // best slots: rs = mt*2 + h  (h: +8-row half of the 16-row tile)
    float best[4];
    int   bi[4];
#pragma unroll
    for (int k = 0; k < 4; k++) { best[k] = -3.402823466e38f; bi[k] = 0; }

    const int pa[6] = {0, 0, 1, 1, 0, 2};
    const int pb[6] = {0, 1, 0, 1, 2, 0};

    for (int ch = 0; ch < NCH; ++ch) {
        int db = ch & 1;
        if (ch + 1 < NCH) prefetch_chunk(sb, db ^ 1, (ch + 1) * CPC, tid);

        float acc[2][4][4];
#pragma unroll
        for (int mt = 0; mt < 2; mt++)
#pragma unroll
            for (int nt = 0; nt < 4; nt++)
#pragma unroll
                for (int q = 0; q < 4; q++) acc[mt][nt][q] = 0.f;

#pragma unroll
        for (int p = 0; p < 6; p++) {
            uint32_t aBase = aLane + pa[p] * 16384;
            uint32_t bBase = bLane + db * 49152 + pb[p] * 16384;
#pragma unroll
            for (int kt = 0; kt < 4; kt++) {
                uint32_t ck = colk[kt];
                uint32_t g0r0, g0r1, g0r2, g0r3, g1r0, g1r1, g1r2, g1r3;
                ldmx4(g0r0, g0r1, g0r2, g0r3, bBase + ck);
                ldmx4(g1r0, g1r1, g1r2, g1r3, bBase + 2048 + ck);
#pragma unroll
                for (int mt = 0; mt < 2; mt++) {
                    uint32_t a0, a1, a2, a3;
                    ldmx4(a0, a1, a2, a3, aBase + mt * 2048 + ck);
                    mma16816(acc[mt][0][0], acc[mt][0][1], acc[mt][0][2], acc[mt][0][3],
                             a0, a1, a2, a3, g0r0, g0r2);
                    mma16816(acc[mt][1][0], acc[mt][1][1], acc[mt][1][2], acc[mt][1][3],
                             a0, a1, a2, a3, g0r1, g0r3);
                    mma16816(acc[mt][2][0], acc[mt][2][1], acc[mt][2][2], acc[mt][2][3],
                             a0, a1, a2, a3, g1r0, g1r2);
                    mma16816(acc[mt][3][0], acc[mt][3][1], acc[mt][3][2], acc[mt][3][3],
                             a0, a1, a2, a3, g1r1, g1r3);
                }
            }
        }

        // ---- epilogue: subtract 0.5||e||^2, running argmax ----
        const float* senp = (const float*)(smem + SEN_OFF + db * 512);
#pragma unroll
        for (int nt = 0; nt < 4; nt++) {
            int nl = Nbase + nt * 8 + (lid & 3) * 2;
            float2 se = *(const float2*)(senp + nl);
            int jb = ch * CPC + nl;
#pragma unroll
            for (int mt = 0; mt < 2; mt++) {
                float s0 = acc[mt][nt][0] - se.x;
                float s1 = acc[mt][nt][1] - se.y;
                float s2 = acc[mt][nt][2] - se.x;
                float s3 = acc[mt][nt][3] - se.y;
                int r0 = mt * 2, r1 = mt * 2 + 1;
                if (s0 > best[r0]) { best[r0] = s0; bi[r0] = jb; }
                if (s1 > best[r0]) { best[r0] = s1; bi[r0] = jb + 1; }
                if (s2 > best[r1]) { best[r1] = s2; bi[r1] = jb; }
                if (s3 > best[r1]) { best[r1] = s3; bi[r1] = jb + 1; }
            }
        }

        if (ch + 1 < NCH) CP_WAIT0();
        __syncthreads();
    }

    // ---- reduce: lanes sharing a row (lid&3), then warps sharing M (wc) ----
    unsigned long long key[4];
#pragma unroll
    for (int rs = 0; rs < 4; rs++) key[rs] = pack_key(best[rs], bi[rs]);
#pragma unroll
    for (int m = 1; m <= 2; m <<= 1) {
#pragma unroll
        for (int rs = 0; rs < 4; rs++) {
            unsigned long long o = __shfl_xor_sync(0xffffffffu, key[rs], m);
            if (o > key[rs]) key[rs] = o;
        }
    }
    unsigned long long* red = (unsigned long long*)(smem + RED_OFF);
    if ((lid & 3) == 0) {
#pragma unroll
        for (int rs = 0; rs < 4; rs++) {
            int mt = rs >> 1, h = rs & 1;
            int row = Mbase + mt * 16 + (lid >> 2) + h * 8;   // row within block
            red[row * 4 + wc] = key[rs];
        }
    }
    __syncthreads();
    if (tid < RPB) {
        unsigned long long k = red[tid * 4];
#pragma unroll
        for (int c = 1; c < 4; c++) { unsigned long long o = red[tid * 4 + c]; if (o > k) k = o; }
        int b = (int)(~(uint32_t)k);
        int row = rowBase + tid;
        g_idx[row] = b;
        out_idxf[row] = (float)b;
    }
}

// ============================================================
__global__ void k_scatter(const float* __restrict__ x) {
    int t = blockIdx.x * 256 + threadIdx.x;
    if (t >= N_ROWS * DIM) return;
    int n = t >> 6, d = t & 63;
    int idx = g_idx[n];
    atomicAdd(&g_embsum[idx * DIM + d], x[t]);
    if (d == 0) atomicAdd(&g_counts[idx], 1.0f);
}

// ============================================================
__global__ void k_cc(const float* __restrict__ cc_in, float* __restrict__ out_cc) {
    int k = blockIdx.x * 256 + threadIdx.x;
    float c = g_counts[k];
    float ncc = cc_in[k] * 0.99f + 0.01f * c;
    out_cc[k] = ncc;
    float p = c * (1.0f / 32768.0f);
    float pl = p * logf(p + 1e-10f);
#pragma unroll
    for (int m = 16; m >= 1; m >>= 1) {
        ncc += __shfl_xor_sync(0xffffffffu, ncc, m);
        pl  += __shfl_xor_sync(0xffffffffu, pl, m);
    }
    __shared__ float s1[8], s2[8];
    int wi = threadIdx.x >> 5, lane = threadIdx.x & 31;
    if (lane == 0) { s1[wi] = ncc; s2[wi] = pl; }
    __syncthreads();
    if (threadIdx.x == 0) {
        float a = 0.f, b = 0.f;
        for (int i = 0; i < 8; i++) { a += s1[i]; b += s2[i]; }
        atomicAdd(&g_nsum, a);
        atomicAdd(&g_plogp, b);
    }
}

// ============================================================
__global__ void k_weight(const float* __restrict__ ws_in, const float* __restrict__ out_cc,
                         float* __restrict__ out_ws, float* __restrict__ out_w) {
    int t = blockIdx.x * 256 + threadIdx.x;
    if (t >= NEMB * DIM) return;
    int k = t >> 6;
    float nws = ws_in[t] * 0.99f + 0.01f * g_embsum[t];
    out_ws[t] = nws;
    float ncc = out_cc[k];
    float n = g_nsum;
    float sm = (ncc + 1e-5f) / (n + (float)NEMB * 1e-5f) * n;
    out_w[t] = nws / sm;
}

// ============================================================
__global__ void k_quant(const float* __restrict__ x, const float* __restrict__ out_w,
                        float* __restrict__ out_q) {
    int t = blockIdx.x * 256 + threadIdx.x;
    if (t >= N_ROWS * DIM) return;
    int n = t >> 6, d = t & 63;
    float q = out_w[g_idx[n] * DIM + d];
    out_q[t] = q;
    float df = q - x[t];
    float v = df * df;
#pragma unroll
    for (int m = 16; m >= 1; m >>= 1) v += __shfl_xor_sync(0xffffffffu, v, m);
    __shared__ float s[8];
    int wi = threadIdx.x >> 5, lane = threadIdx.x & 31;
    if (lane == 0) s[wi] = v;
    __syncthreads();
    if (threadIdx.x == 0) {
        float a = 0.f;
        for (int i = 0; i < 8; i++) a += s[i];
        atomicAdd(&g_loss, a);
    }
}

// ============================================================
__global__ void k_scalars(float* __restrict__ out) {
    out[OFF_LOSS] = 0.25f * g_loss * (1.0f / 2097152.0f);
    out[OFF_PERP] = expf(-g_plogp);
}

// ============================================================
extern "C" void kernel_launch(void* const* d_in, const int* in_sizes, int n_in,
                              void* d_out, int out_size) {
    const float* x  = (const float*)d_in[0];
    const float* w  = (const float*)d_in[1];
    const float* cc = (const float*)d_in[2];
    const float* ws = (const float*)d_in[3];
    float* out = (float*)d_out;

    cudaFuncSetAttribute(k_argmin_mma, cudaFuncAttributeMaxDynamicSharedMemorySize,
                         SMEM_BYTES);

    k_init      <<<2048, 256>>>();
    k_prep      <<<2048, 256>>>(w);
    k_enorm     <<<1024, 256>>>(w);
    k_argmin_mma<<<N_ROWS / RPB, NTHR, SMEM_BYTES>>>(x, out + OFF_IDX);
    k_scatter   <<<8192, 256>>>(x);
    k_cc        <<<32,   256>>>(cc, out + OFF_CC);
    k_weight    <<<2048, 256>>>(ws, out + OFF_CC, out + OFF_WS, out + OFF_W);
    k_quant     <<<8192, 256>>>(x, out + OFF_W, out + OFF_Q);
    k_scalars   <<<1, 1>>>(out);
}

// round 12
// speedup vs baseline: 1.2221x; 1.2221x over previous
#include <cuda_runtime.h>
#include <cuda_bf16.h>
#include <cstdint>
#include <math.h>

#define N_ROWS 32768
#define DIM    64
#define NEMB   8192

// ---- output layout (concatenated reference tuple, all float32) ----
#define OFF_Q    0
#define OFF_LOSS 2097152
#define OFF_IDX  2097153
#define OFF_PERP 2129921
#define OFF_W    2129922
#define OFF_CC   2654210
#define OFF_WS   2662402

// ---- argmin tiling ----
#define RPB   128            // rows per block (M)
#define CPC   128            // codes per chunk (N)
#define NCH   (NEMB/CPC)     // 64 chunks
#define NTHR  512            // 16 warps: 4(M) x 4(N)

// SMEM layout (bytes). Tiles: 128 rows x 128B (64 bf16), XOR-swizzled.
#define A_OFF      0                      // 3 x 16KB (h,m,l splits of x rows)
#define B_OFF      49152                  // 2 bufs x 3 x 16KB
#define SEN_OFF    147456                 // 2 x 512B (0.5*||e||^2 per chunk)
#define RED_OFF    148480                 // 128 rows x 4 warpcols x 8B
#define SMEM_BYTES 152576

// ---- device scratch ----
__device__ int   g_idx[N_ROWS];
__device__ float g_counts[NEMB];
__device__ float g_embsum[NEMB * DIM];
__device__ float g_enormh[NEMB];
__device__ float g_nsum;
__device__ float g_loss;
__device__ float g_plogp;
// pre-split codebook (3-term bf16 decomposition of w)
__device__ __nv_bfloat16 g_wh[NEMB * DIM];
__device__ __nv_bfloat16 g_wm[NEMB * DIM];
__device__ __nv_bfloat16 g_wl[NEMB * DIM];

// ================= helpers =================
__device__ __forceinline__ uint32_t smem_u32_of(const void* p) {
    uint32_t a;
    asm("{ .reg .u64 t; cvta.to.shared.u64 t, %1; cvt.u32.u64 %0, t; }"
        : "=r"(a) : "l"(p));
    return a;
}
__device__ __forceinline__ void ldmx4(uint32_t& r0, uint32_t& r1, uint32_t& r2,
                                      uint32_t& r3, uint32_t a) {
    asm volatile("ldmatrix.sync.aligned.m8n8.x4.shared.b16 {%0,%1,%2,%3}, [%4];"
                 : "=r"(r0), "=r"(r1), "=r"(r2), "=r"(r3) : "r"(a));
}
__device__ __forceinline__ void mma16816(float& c0, float& c1, float& c2, float& c3,
                                         uint32_t a0, uint32_t a1, uint32_t a2, uint32_t a3,
                                         uint32_t b0, uint32_t b1) {
    asm volatile("mma.sync.aligned.m16n8k16.row.col.f32.bf16.bf16.f32 "
                 "{%0,%1,%2,%3}, {%4,%5,%6,%7}, {%8,%9}, {%0,%1,%2,%3};"
                 : "+f"(c0), "+f"(c1), "+f"(c2), "+f"(c3)
                 : "r"(a0), "r"(a1), "r"(a2), "r"(a3), "r"(b0), "r"(b1));
}
__device__ __forceinline__ void cp16(uint32_t dst, const void* src) {
    asm volatile("cp.async.cg.shared.global [%0], [%1], 16;" :: "r"(dst), "l"(src));
}
#define CP_COMMIT() asm volatile("cp.async.commit_group;" ::: "memory")
#define CP_WAIT0()  asm volatile("cp.async.wait_group 0;" ::: "memory")

__device__ __forceinline__ uint32_t pack_bf2(__nv_bfloat16 a, __nv_bfloat16 b) {
    unsigned short ua = *(unsigned short*)&a, ub = *(unsigned short*)&b;
    return (uint32_t)ua | ((uint32_t)ub << 16);
}
__device__ __forceinline__ unsigned long long pack_key(float s, int j) {
    uint32_t u = __float_as_uint(s);
    u = (u & 0x80000000u) ? ~u : (u | 0x80000000u);   // order-preserving
    return ((unsigned long long)u << 32) | (uint32_t)(~j);  // bigger = better; ties -> smaller j
}

// ============================================================
__global__ void k_init() {
    int t = blockIdx.x * 256 + threadIdx.x;
    if (t < NEMB * DIM) g_embsum[t] = 0.f;
    if (t < NEMB)       g_counts[t] = 0.f;
    if (t == 0) { g_nsum = 0.f; g_loss = 0.f; g_plogp = 0.f; }
}

// 3-way bf16 split of the codebook
__global__ void k_prep(const float* __restrict__ w) {
    int t = blockIdx.x * 256 + threadIdx.x;
    float v = w[t];
    __nv_bfloat16 h = __float2bfloat16_rn(v);
    float r1 = v - __bfloat162float(h);
    __nv_bfloat16 m = __float2bfloat16_rn(r1);
    float r2 = r1 - __bfloat162float(m);
    __nv_bfloat16 l = __float2bfloat16_rn(r2);
    g_wh[t] = h; g_wm[t] = m; g_wl[t] = l;
}

__global__ void k_enorm(const float* __restrict__ w) {
    int code = blockIdx.x * 8 + (threadIdx.x >> 5);
    int lane = threadIdx.x & 31;
    float a = w[code * DIM + lane];
    float b = w[code * DIM + 32 + lane];
    float s = a * a + b * b;
#pragma unroll
    for (int m = 16; m >= 1; m >>= 1) s += __shfl_xor_sync(0xffffffffu, s, m);
    if (lane == 0) g_enormh[code] = 0.5f * s;
}

// ============================================================
// tensor-core argmin via mma.sync. 512 threads, warp grid 4Mx4N.
// A fragments register-resident (loaded once, reused 64 chunks);
// B fragments loaded once per split per chunk and reused by all
// products sharing that B split -> LDSM:MMA = 1:8 in steady state.
// ============================================================
__device__ __forceinline__ void prefetch_chunk(uint32_t sb, int buf, int cbase, int tid) {
    const __nv_bfloat16* wsp0 = g_wh;
    const __nv_bfloat16* wsp1 = g_wm;
    const __nv_bfloat16* wsp2 = g_wl;
#pragma unroll
    for (int i = 0; i < 6; i++) {
        int u = tid + i * NTHR;               // 3 splits * 128 rows * 8 col16 = 3072
        int s = u >> 10;
        int rem = u & 1023;
        int row = rem >> 3, c16 = rem & 7;
        uint32_t dst = sb + B_OFF + buf * 49152 + s * 16384 +
                       row * 128 + (((uint32_t)(c16 ^ (row & 7))) << 4);
        const __nv_bfloat16* wsp = (s == 0) ? wsp0 : (s == 1) ? wsp1 : wsp2;
        cp16(dst, wsp + (size_t)(cbase + row) * 64 + c16 * 8);
    }
    if (tid >= NTHR - 32) {                   // sen: 128 floats = 32 x 16B
        int u = tid - (NTHR - 32);
        cp16(sb + SEN_OFF + buf * 512 + u * 16, g_enormh + cbase + u * 4);
    }
    CP_COMMIT();
}

__global__ void __launch_bounds__(NTHR, 1) k_argmin_mma(const float* __restrict__ x,
                                                        float* __restrict__ out_idxf) {
    extern __shared__ __align__(16) char smem[];
    uint32_t sb = smem_u32_of(smem);
    int tid = threadIdx.x;
    int wid = tid >> 5;
    int lid = tid & 31;
    int rowBase = blockIdx.x * RPB;

    int wr = wid & 3;          // M slab (32 rows)
    int wc = wid >> 2;         // N slab (32 codes)
    int Mbase = wr * 32;
    int Nbase = wc * 32;

    // ldmatrix lane geometry (same for A and B)
    int ri    = lid & 7;
    int mi    = lid >> 3;
    int rowIn = (mi & 1) * 8 + ri;   // row within 16-row tile
    int half  = mi >> 1;             // col16 half within tile
    uint32_t colk[4];
#pragma unroll
    for (int kt = 0; kt < 4; kt++) colk[kt] = (uint32_t)((kt * 2 + half) ^ ri) << 4;
    uint32_t aLane = sb + A_OFF + (uint32_t)(Mbase + rowIn) * 128;
    uint32_t bLane = sb + B_OFF + (uint32_t)(Nbase + rowIn) * 128;

    // kick off B prefetch for chunk 0
    prefetch_chunk(sb, 0, 0, tid);

    // ---- A fill: split 128x64 f32 rows into 3 swizzled bf16 tiles ----
#pragma unroll
    for (int i = 0; i < 2; i++) {
        int u = tid + i * NTHR;              // 128 rows * 8 col16 = 1024
        int row = u >> 3, c16 = u & 7;
        const float* src = x + (size_t)(rowBase + row) * 64 + c16 * 8;
        float4 f0 = *(const float4*)src;
        float4 f1 = *(const float4*)(src + 4);
        float v[8] = {f0.x, f0.y, f0.z, f0.w, f1.x, f1.y, f1.z, f1.w};
        __nv_bfloat16 hb[8], mb[8], lb[8];
#pragma unroll
        for (int j = 0; j < 8; j++) {
            __nv_bfloat16 h = __float2bfloat16_rn(v[j]);
            float r1 = v[j] - __bfloat162float(h);
            __nv_bfloat16 m = __float2bfloat16_rn(r1);
            float r2 = r1 - __bfloat162float(m);
            hb[j] = h; mb[j] = m; lb[j] = __float2bfloat16_rn(r2);
        }
        uint32_t off = (uint32_t)row * 128 + (((uint32_t)(c16 ^ (row & 7))) << 4);
        uint4 ph = make_uint4(pack_bf2(hb[0], hb[1]), pack_bf2(hb[2], hb[3]),
                              pack_bf2(hb[4], hb[5]), pack_bf2(hb[6], hb[7]));
        uint4 pm = make_uint4(pack_bf2(mb[0], mb[1]), pack_bf2(mb[2], mb[3]),
                              pack_bf2(mb[4], mb[5]), pack_bf2(mb[6], mb[7]));
        uint4 pl = make_uint4(pack_bf2(lb[0], lb[1]), pack_bf2(lb[2], lb[3]),
                              pack_bf2(lb[4], lb[5]), pack_bf2(lb[6], lb[7]));
        *(uint4*)(smem + A_OFF + off)           = ph;
        *(uint4*)(smem + A_OFF + 16384 + off)   = pm;
        *(uint4*)(smem + A_OFF + 32768 + off)   = pl;
    }
    __syncthreads();

    // ---- load A fragments into registers (resident for all chunks) ----
    uint32_t afr[3][2][4][4];
#pragma unroll
    for (int s = 0; s < 3; s++)
#pragma unroll
        for (int mt = 0; mt < 2; mt++)
#pragma unroll
            for (int kt = 0; kt < 4; kt++)
                ldmx4(afr[s][mt][kt][0], afr[s][mt][kt][1],
                      afr[s][mt][kt][2], afr[s][mt][kt][3],
                      aLane + s * 16384 + mt * 2048 + colk[kt]);

    CP_WAIT0();
    __syncthreads();

    float best[4];
    int   bi[4];
#pragma unroll
    for (int k = 0; k < 4; k++) { best[k] = -3.402823466e38f; bi[k] = 0; }

#define LOADB(s_) do {                                                        \
    _Pragma("unroll")                                                         \
    for (int kt = 0; kt < 4; kt++) {                                          \
        ldmx4(bfr[kt][0], bfr[kt][1], bfr[kt][2], bfr[kt][3],                 \
              bB + (s_) * 16384 + colk[kt]);                                  \
        ldmx4(bfr[kt][4], bfr[kt][5], bfr[kt][6], bfr[kt][7],                 \
              bB + (s_) * 16384 + 2048 + colk[kt]);                           \
    } } while (0)

#define PROD(pa_) do {                                                        \
    _Pragma("unroll")                                                         \
    for (int kt = 0; kt < 4; kt++) {                                          \
        _Pragma("unroll")                                                     \
        for (int mt = 0; mt < 2; mt++) {                                      \
            mma16816(acc[mt][0][0], acc[mt][0][1], acc[mt][0][2], acc[mt][0][3], \
                     afr[pa_][mt][kt][0], afr[pa_][mt][kt][1],                \
                     afr[pa_][mt][kt][2], afr[pa_][mt][kt][3],                \
                     bfr[kt][0], bfr[kt][2]);                                 \
            mma16816(acc[mt][1][0], acc[mt][1][1], acc[mt][1][2], acc[mt][1][3], \
                     afr[pa_][mt][kt][0], afr[pa_][mt][kt][1],                \
                     afr[pa_][mt][kt][2], afr[pa_][mt][kt][3],                \
                     bfr[kt][1], bfr[kt][3]);                                 \
            mma16816(acc[mt][2][0], acc[mt][2][1], acc[mt][2][2], acc[mt][2][3], \
                     afr[pa_][mt][kt][0], afr[pa_][mt][kt][1],                \
                     afr[pa_][mt][kt][2], afr[pa_][mt][kt][3],                \
                     bfr[kt][4], bfr[kt][6]);                                 \
            mma16816(acc[mt][3][0], acc[mt][3][1], acc[mt][3][2], acc[mt][3][3], \
                     afr[pa_][mt][kt][0], afr[pa_][mt][kt][1],                \
                     afr[pa_][mt][kt][2], afr[pa_][mt][kt][3],                \
                     bfr[kt][5], bfr[kt][7]);                                 \
        } } } while (0)

    for (int ch = 0; ch < NCH; ++ch) {
        int db = ch & 1;
        if (ch + 1 < NCH) prefetch_chunk(sb, db ^ 1, (ch + 1) * CPC, tid);

        float acc[2][4][4];
#pragma unroll
        for (int mt = 0; mt < 2; mt++)
#pragma unroll
            for (int nt = 0; nt < 4; nt++)
#pragma unroll
                for (int q = 0; q < 4; q++) acc[mt][nt][q] = 0.f;

        uint32_t bB = bLane + db * 49152;
        uint32_t bfr[4][8];

        // products grouped by B split: set = {hh, mh, lh, hm, mm, hl}
        LOADB(0);           // B = h
        PROD(0);            // hh
        PROD(1);            // mh
        PROD(2);            // lh
        LOADB(1);           // B = m
        PROD(0);            // hm
        PROD(1);            // mm
        LOADB(2);           // B = l
        PROD(0);            // hl

        // ---- epilogue: subtract 0.5||e||^2, running argmax ----
        const float* senp = (const float*)(smem + SEN_OFF + db * 512);
#pragma unroll
        for (int nt = 0; nt < 4; nt++) {
            int nl = Nbase + nt * 8 + (lid & 3) * 2;
            float2 se = *(const float2*)(senp + nl);
            int jb = ch * CPC + nl;
#pragma unroll
            for (int mt = 0; mt < 2; mt++) {
                float s0 = acc[mt][nt][0] - se.x;
                float s1 = acc[mt][nt][1] - se.y;
                float s2 = acc[mt][nt][2] - se.x;
                float s3 = acc[mt][nt][3] - se.y;
                int r0 = mt * 2, r1 = mt * 2 + 1;
                if (s0 > best[r0]) { best[r0] = s0; bi[r0] = jb; }
                if (s1 > best[r0]) { best[r0] = s1; bi[r0] = jb + 1; }
                if (s2 > best[r1]) { best[r1] = s2; bi[r1] = jb; }
                if (s3 > best[r1]) { best[r1] = s3; bi[r1] = jb + 1; }
            }
        }

        if (ch + 1 < NCH) CP_WAIT0();
        __syncthreads();
    }
#undef LOADB
#undef PROD

    // ---- reduce: lanes sharing a row (lid&3), then warps sharing M (wc) ----
    unsigned long long key[4];
#pragma unroll
    for (int rs = 0; rs < 4; rs++) key[rs] = pack_key(best[rs], bi[rs]);
#pragma unroll
    for (int m = 1; m <= 2; m <<= 1) {
#pragma unroll
        for (int rs = 0; rs < 4; rs++) {
            unsigned long long o = __shfl_xor_sync(0xffffffffu, key[rs], m);
            if (o > key[rs]) key[rs] = o;
        }
    }
    unsigned long long* red = (unsigned long long*)(smem + RED_OFF);
    if ((lid & 3) == 0) {
#pragma unroll
        for (int rs = 0; rs < 4; rs++) {
            int mt = rs >> 1, h = rs & 1;
            int row = Mbase + mt * 16 + (lid >> 2) + h * 8;   // row within block
            red[row * 4 + wc] = key[rs];
        }
    }
    __syncthreads();
    if (tid < RPB) {
        unsigned long long k = red[tid * 4];
#pragma unroll
        for (int c = 1; c < 4; c++) { unsigned long long o = red[tid * 4 + c]; if (o > k) k = o; }
        int b = (int)(~(uint32_t)k);
        int row = rowBase + tid;
        g_idx[row] = b;
        out_idxf[row] = (float)b;
    }
}

// ============================================================
__global__ void k_scatter(const float* __restrict__ x) {
    int t = blockIdx.x * 256 + threadIdx.x;
    if (t >= N_ROWS * DIM) return;
    int n = t >> 6, d = t & 63;
    int idx = g_idx[n];
    atomicAdd(&g_embsum[idx * DIM + d], x[t]);
    if (d == 0) atomicAdd(&g_counts[idx], 1.0f);
}

// ============================================================
__global__ void k_cc(const float* __restrict__ cc_in, float* __restrict__ out_cc) {
    int k = blockIdx.x * 256 + threadIdx.x;
    float c = g_counts[k];
    float ncc = cc_in[k] * 0.99f + 0.01f * c;
    out_cc[k] = ncc;
    float p = c * (1.0f / 32768.0f);
    float pl = p * logf(p + 1e-10f);
#pragma unroll
    for (int m = 16; m >= 1; m >>= 1) {
        ncc += __shfl_xor_sync(0xffffffffu, ncc, m);
        pl  += __shfl_xor_sync(0xffffffffu, pl, m);
    }
    __shared__ float s1[8], s2[8];
    int wi = threadIdx.x >> 5, lane = threadIdx.x & 31;
    if (lane == 0) { s1[wi] = ncc; s2[wi] = pl; }
    __syncthreads();
    if (threadIdx.x == 0) {
        float a = 0.f, b = 0.f;
        for (int i = 0; i < 8; i++) { a += s1[i]; b += s2[i]; }
        atomicAdd(&g_nsum, a);
        atomicAdd(&g_plogp, b);
    }
}

// ============================================================
__global__ void k_weight(const float* __restrict__ ws_in, const float* __restrict__ out_cc,
                         float* __restrict__ out_ws, float* __restrict__ out_w) {
    int t = blockIdx.x * 256 + threadIdx.x;
    if (t >= NEMB * DIM) return;
    int k = t >> 6;
    float nws = ws_in[t] * 0.99f + 0.01f * g_embsum[t];
    out_ws[t] = nws;
    float ncc = out_cc[k];
    float n = g_nsum;
    float sm = (ncc + 1e-5f) / (n + (float)NEMB * 1e-5f) * n;
    out_w[t] = nws / sm;
}

// ============================================================
__global__ void k_quant(const float* __restrict__ x, const float* __restrict__ out_w,
                        float* __restrict__ out_q) {
    int t = blockIdx.x * 256 + threadIdx.x;
    if (t >= N_ROWS * DIM) return;
    int n = t >> 6, d = t & 63;
    float q = out_w[g_idx[n] * DIM + d];
    out_q[t] = q;
    float df = q - x[t];
    float v = df * df;
#pragma unroll
    for (int m = 16; m >= 1; m >>= 1) v += __shfl_xor_sync(0xffffffffu, v, m);
    __shared__ float s[8];
    int wi = threadIdx.x >> 5, lane = threadIdx.x & 31;
    if (lane == 0) s[wi] = v;
    __syncthreads();
    if (threadIdx.x == 0) {
        float a = 0.f;
        for (int i = 0; i < 8; i++) a += s[i];
        atomicAdd(&g_loss, a);
    }
}

// ============================================================
__global__ void k_scalars(float* __restrict__ out) {
    out[OFF_LOSS] = 0.25f * g_loss * (1.0f / 2097152.0f);
    out[OFF_PERP] = expf(-g_plogp);
}

// ============================================================
extern "C" void kernel_launch(void* const* d_in, const int* in_sizes, int n_in,
                              void* d_out, int out_size) {
    const float* x  = (const float*)d_in[0];
    const float* w  = (const float*)d_in[1];
    const float* cc = (const float*)d_in[2];
    const float* ws = (const float*)d_in[3];
    float* out = (float*)d_out;

    cudaFuncSetAttribute(k_argmin_mma, cudaFuncAttributeMaxDynamicSharedMemorySize,
                         SMEM_BYTES);

    k_init      <<<2048, 256>>>();
    k_prep      <<<2048, 256>>>(w);
    k_enorm     <<<1024, 256>>>(w);
    k_argmin_mma<<<N_ROWS / RPB, NTHR, SMEM_BYTES>>>(x, out + OFF_IDX);
    k_scatter   <<<8192, 256>>>(x);
    k_cc        <<<32,   256>>>(cc, out + OFF_CC);
    k_weight    <<<2048, 256>>>(ws, out + OFF_CC, out + OFF_WS, out + OFF_W);
    k_quant     <<<8192, 256>>>(x, out + OFF_W, out + OFF_Q);
    k_scalars   <<<1, 1>>>(out);
}